// round 2
// baseline (speedup 1.0000x reference)
#include <cuda_runtime.h>
#include <cuda_bf16.h>
#include <cstdint>

#define BATCH 4
#define NSEQ  4096
#define DIM   512
#define ABS   64
#define NT    64          // tiles of 64 rows per batch (NSEQ/ABS)

// -------- scratch (device globals; no runtime allocation) --------
__device__ float g_c[BATCH * NSEQ * DIM];        // normalized data (32 MB)
__device__ float g_S0[BATCH * NT * ABS * DIM];   // exclusive tile-prefix sums (32 MB)
__device__ float g_pooled[BATCH * NSEQ * ABS];   // [B,N,64] (4 MB)
__device__ float g_Wc[ABS * DIM];                // W_abs @ W_merge[512:1024] (128 KB)

// ============================================================
// Kernel A: L2 normalize rows of data -> g_c
// grid = B*N blocks, 128 threads (each thread: one float4 of the 512-dim row)
// ============================================================
__global__ void k_norm(const float* __restrict__ data) {
    int row = blockIdx.x;                       // 0 .. 16383
    const float4* src = (const float4*)(data + (size_t)row * DIM);
    float4*       dst = (float4*)(g_c + (size_t)row * DIM);
    int t = threadIdx.x;

    float4 v = src[t];
    float s = v.x * v.x + v.y * v.y + v.z * v.z + v.w * v.w;
    #pragma unroll
    for (int off = 16; off > 0; off >>= 1)
        s += __shfl_xor_sync(0xFFFFFFFFu, s, off);

    __shared__ float ws[4];
    __shared__ float s_inv;
    int lane = t & 31, warp = t >> 5;
    if (lane == 0) ws[warp] = s;
    __syncthreads();
    if (t == 0) {
        float tot = ws[0] + ws[1] + ws[2] + ws[3];
        s_inv = rsqrtf(fmaxf(tot, 1e-12f));
    }
    __syncthreads();
    float iv = s_inv;
    v.x *= iv; v.y *= iv; v.z *= iv; v.w *= iv;
    dst[t] = v;
}

// ============================================================
// Kernel B: exclusive prefix scan over tile index.
// S0[b,t,a,:] = sum_{g<t} c[b, g*64+a, :]
// one thread per (b, a, d4): 4*64*128 = 32768 threads
// ============================================================
__global__ void k_scan() {
    int idx = blockIdx.x * blockDim.x + threadIdx.x;   // 0..32767
    int b  = idx >> 13;          // / (64*128)
    int r  = idx & 8191;
    int a  = r >> 7;             // residue class
    int d4 = r & 127;            // float4 index within DIM

    float4 acc = make_float4(0.f, 0.f, 0.f, 0.f);
    const float4* cbase = (const float4*)g_c;
    float4*       sbase = (float4*)g_S0;
    #pragma unroll 4
    for (int g = 0; g < NT; ++g) {
        size_t sidx = ((size_t)((b * NT + g) * ABS + a)) * (DIM / 4) + d4;
        sbase[sidx] = acc;                                   // exclusive
        size_t cidx = ((size_t)(b * NSEQ + g * ABS + a)) * (DIM / 4) + d4;
        float4 v = cbase[cidx];
        acc.x += v.x; acc.y += v.y; acc.z += v.z; acc.w += v.w;
    }
}

// ============================================================
// Kernel C: pooled[b, t*64+i, a] =
//   (1/64) * ( c_i . S0[t,a]  +  (a<=i) * c_i . c_a_local )
// One CTA per (b, t): two fused 64x64x512 GEMMs sharing the A operand.
// 256 threads, 4x4 micro-tile per thread per GEMM.
// ============================================================
#define KC 64
__global__ void __launch_bounds__(256) k_pooled() {
    __shared__ float cs[KC][68];   // K-major c tile   (pad 68 -> 272B rows, 16B aligned)
    __shared__ float ss[KC][68];   // K-major S0 tile

    int bt = blockIdx.x;
    int b = bt >> 6, t = bt & 63;
    const float* cbase = g_c  + ((size_t)b * NSEQ + t * ABS) * DIM;   // 64 x 512
    const float* sbase = g_S0 + ((size_t)(b * NT + t)) * ABS * DIM;   // 64 x 512

    int tid = threadIdx.x;
    int tx = tid & 15, ty = tid >> 4;

    float ah[4][4], ad[4][4];
    #pragma unroll
    for (int m = 0; m < 4; ++m)
        #pragma unroll
        for (int n = 0; n < 4; ++n) { ah[m][n] = 0.f; ad[m][n] = 0.f; }

    for (int k0 = 0; k0 < DIM; k0 += KC) {
        // load 64x64 chunk of both tiles, transposed into K-major smem
        #pragma unroll
        for (int j = 0; j < 4; ++j) {
            int f = tid + 256 * j;           // 0..1023 float4s
            int row = f >> 4;                // 0..63
            int cq  = f & 15;                // which float4 within 64 cols
            float4 v = *(const float4*)(cbase + (size_t)row * DIM + k0 + cq * 4);
            cs[cq * 4 + 0][row] = v.x; cs[cq * 4 + 1][row] = v.y;
            cs[cq * 4 + 2][row] = v.z; cs[cq * 4 + 3][row] = v.w;
            float4 w = *(const float4*)(sbase + (size_t)row * DIM + k0 + cq * 4);
            ss[cq * 4 + 0][row] = w.x; ss[cq * 4 + 1][row] = w.y;
            ss[cq * 4 + 2][row] = w.z; ss[cq * 4 + 3][row] = w.w;
        }
        __syncthreads();

        #pragma unroll 8
        for (int kk = 0; kk < KC; ++kk) {
            float4 af = *(const float4*)&cs[kk][ty * 4];
            float4 bh = *(const float4*)&ss[kk][tx * 4];
            float4 bd = *(const float4*)&cs[kk][tx * 4];
            float a_[4] = {af.x, af.y, af.z, af.w};
            float h_[4] = {bh.x, bh.y, bh.z, bh.w};
            float d_[4] = {bd.x, bd.y, bd.z, bd.w};
            #pragma unroll
            for (int m = 0; m < 4; ++m)
                #pragma unroll
                for (int n = 0; n < 4; ++n) {
                    ah[m][n] += a_[m] * h_[n];
                    ad[m][n] += a_[m] * d_[n];
                }
        }
        __syncthreads();
    }

    // write pooled with causal diag mask and 1/64 scale
    const float scale = 1.0f / 64.0f;
    #pragma unroll
    for (int m = 0; m < 4; ++m) {
        int i = ty * 4 + m;
        float* orow = g_pooled + ((size_t)b * NSEQ + t * ABS + i) * ABS;
        #pragma unroll
        for (int n = 0; n < 4; ++n) {
            int j = tx * 4 + n;
            float v = ah[m][n] + ((j <= i) ? ad[m][n] : 0.f);
            orow[j] = v * scale;
        }
    }
}

// ============================================================
// Kernel Wc: W_comb[a, dout] = sum_k W_abs[a,k] * W_merge[512+k, dout]
// (64x512x512 = tiny)
// ============================================================
__global__ void k_wc(const float* __restrict__ Wabs, const float* __restrict__ Wm) {
    int idx = blockIdx.x * blockDim.x + threadIdx.x;   // 0..32767
    int a = idx >> 9;
    int dout = idx & 511;
    float acc = 0.f;
    #pragma unroll 8
    for (int k = 0; k < DIM; ++k)
        acc = fmaf(Wabs[a * DIM + k], Wm[(size_t)(DIM + k) * DIM + dout], acc);
    g_Wc[idx] = acc;
}

// ============================================================
// Kernel D: merged = data @ W1 + pooled @ W_comb
// M=16384, N=512, K=512 then K=64. Classic 128x128 SGEMM, 8x8/thread.
// ============================================================
__global__ void __launch_bounds__(256) k_gemm(const float* __restrict__ data,
                                              const float* __restrict__ Wm,
                                              float* __restrict__ out) {
    __shared__ float As[16][132];   // K-major A (row 528B, 16B aligned)
    __shared__ float Bs[16][128];

    int tid = threadIdx.x;
    int tx = tid & 15, ty = tid >> 4;
    int m0 = blockIdx.y * 128;
    int n0 = blockIdx.x * 128;

    float acc[8][8];
    #pragma unroll
    for (int m = 0; m < 8; ++m)
        #pragma unroll
        for (int n = 0; n < 8; ++n) acc[m][n] = 0.f;

    // ---- phase 1: data @ W1 (K = 512) ----
    for (int k0 = 0; k0 < DIM; k0 += 16) {
        #pragma unroll
        for (int j = 0; j < 2; ++j) {
            int f = tid + 256 * j;                 // 0..511 float4s
            int row = f >> 2, q = f & 3;           // A: 128 rows x 4 quads
            float4 v = *(const float4*)(data + (size_t)(m0 + row) * DIM + k0 + q * 4);
            As[q * 4 + 0][row] = v.x; As[q * 4 + 1][row] = v.y;
            As[q * 4 + 2][row] = v.z; As[q * 4 + 3][row] = v.w;
            int rb = f >> 5, qb = f & 31;          // B: 16 rows x 32 quads
            float4 w = *(const float4*)(Wm + (size_t)(k0 + rb) * DIM + n0 + qb * 4);
            *(float4*)&Bs[rb][qb * 4] = w;
        }
        __syncthreads();
        #pragma unroll
        for (int kk = 0; kk < 16; ++kk) {
            float4 a0 = *(const float4*)&As[kk][ty * 4];
            float4 a1 = *(const float4*)&As[kk][ty * 4 + 64];
            float4 b0 = *(const float4*)&Bs[kk][tx * 4];
            float4 b1 = *(const float4*)&Bs[kk][tx * 4 + 64];
            float ar[8] = {a0.x, a0.y, a0.z, a0.w, a1.x, a1.y, a1.z, a1.w};
            float br[8] = {b0.x, b0.y, b0.z, b0.w, b1.x, b1.y, b1.z, b1.w};
            #pragma unroll
            for (int m = 0; m < 8; ++m)
                #pragma unroll
                for (int n = 0; n < 8; ++n)
                    acc[m][n] = fmaf(ar[m], br[n], acc[m][n]);
        }
        __syncthreads();
    }

    // ---- phase 2: pooled @ W_comb (K = 64) ----
    const float* __restrict__ pbase = g_pooled;
    const float* __restrict__ wbase = g_Wc;
    for (int k0 = 0; k0 < ABS; k0 += 16) {
        #pragma unroll
        for (int j = 0; j < 2; ++j) {
            int f = tid + 256 * j;
            int row = f >> 2, q = f & 3;
            float4 v = *(const float4*)(pbase + (size_t)(m0 + row) * ABS + k0 + q * 4);
            As[q * 4 + 0][row] = v.x; As[q * 4 + 1][row] = v.y;
            As[q * 4 + 2][row] = v.z; As[q * 4 + 3][row] = v.w;
            int rb = f >> 5, qb = f & 31;
            float4 w = *(const float4*)(wbase + (size_t)(k0 + rb) * DIM + n0 + qb * 4);
            *(float4*)&Bs[rb][qb * 4] = w;
        }
        __syncthreads();
        #pragma unroll
        for (int kk = 0; kk < 16; ++kk) {
            float4 a0 = *(const float4*)&As[kk][ty * 4];
            float4 a1 = *(const float4*)&As[kk][ty * 4 + 64];
            float4 b0 = *(const float4*)&Bs[kk][tx * 4];
            float4 b1 = *(const float4*)&Bs[kk][tx * 4 + 64];
            float ar[8] = {a0.x, a0.y, a0.z, a0.w, a1.x, a1.y, a1.z, a1.w};
            float br[8] = {b0.x, b0.y, b0.z, b0.w, b1.x, b1.y, b1.z, b1.w};
            #pragma unroll
            for (int m = 0; m < 8; ++m)
                #pragma unroll
                for (int n = 0; n < 8; ++n)
                    acc[m][n] = fmaf(ar[m], br[n], acc[m][n]);
        }
        __syncthreads();
    }

    // ---- epilogue ----
    #pragma unroll
    for (int m = 0; m < 8; ++m) {
        int r = m0 + ((m < 4) ? (ty * 4 + m) : (64 + ty * 4 + m - 4));
        float4 v0 = make_float4(acc[m][0], acc[m][1], acc[m][2], acc[m][3]);
        float4 v1 = make_float4(acc[m][4], acc[m][5], acc[m][6], acc[m][7]);
        *(float4*)(out + (size_t)r * DIM + n0 + tx * 4)      = v0;
        *(float4*)(out + (size_t)r * DIM + n0 + 64 + tx * 4) = v1;
    }
}

// ============================================================
extern "C" void kernel_launch(void* const* d_in, const int* in_sizes, int n_in,
                              void* d_out, int out_size) {
    const float* data = (const float*)d_in[0];   // [4,4096,512]
    const float* Wabs = (const float*)d_in[1];   // [64,512]
    const float* Wm   = (const float*)d_in[2];   // [1024,512]
    float* out = (float*)d_out;                  // [4,4096,512]

    k_norm<<<BATCH * NSEQ, 128>>>(data);
    k_wc<<<128, 256>>>(Wabs, Wm);                // independent, tiny
    k_scan<<<128, 256>>>();
    k_pooled<<<BATCH * NT, 256>>>();
    k_gemm<<<dim3(DIM / 128, BATCH * NSEQ / 128), 256>>>(data, Wm, out);
}

// round 3
// speedup vs baseline: 1.1286x; 1.1286x over previous
#include <cuda_runtime.h>
#include <cuda_bf16.h>
#include <cstdint>

#define BATCH 4
#define NSEQ  4096
#define DIM   512
#define ABS   64
#define NT    64          // tiles of 64 rows per batch (NSEQ/ABS)

// -------- scratch (device globals; no runtime allocation) --------
__device__ float g_c[BATCH * NSEQ * DIM];        // normalized data (32 MB)
__device__ float g_S0[BATCH * NT * ABS * DIM];   // exclusive tile-prefix sums (32 MB)
__device__ float g_pooled[BATCH * NSEQ * ABS];   // [B,N,64] (4 MB)
__device__ float g_Wc[ABS * DIM];                // W_abs @ W_merge[512:1024] (128 KB)

// ============================================================
// Kernel A: L2 normalize rows of data -> g_c
// ============================================================
__global__ void k_norm(const float* __restrict__ data) {
    int row = blockIdx.x;                       // 0 .. 16383
    const float4* src = (const float4*)(data + (size_t)row * DIM);
    float4*       dst = (float4*)(g_c + (size_t)row * DIM);
    int t = threadIdx.x;

    float4 v = src[t];
    float s = v.x * v.x + v.y * v.y + v.z * v.z + v.w * v.w;
    #pragma unroll
    for (int off = 16; off > 0; off >>= 1)
        s += __shfl_xor_sync(0xFFFFFFFFu, s, off);

    __shared__ float ws[4];
    __shared__ float s_inv;
    int lane = t & 31, warp = t >> 5;
    if (lane == 0) ws[warp] = s;
    __syncthreads();
    if (t == 0) {
        float tot = ws[0] + ws[1] + ws[2] + ws[3];
        s_inv = rsqrtf(fmaxf(tot, 1e-12f));
    }
    __syncthreads();
    float iv = s_inv;
    v.x *= iv; v.y *= iv; v.z *= iv; v.w *= iv;
    dst[t] = v;
}

// ============================================================
// Kernel B: exclusive prefix scan over tile index.
// S0[b,t,a,:] = sum_{g<t} c[b, g*64+a, :]
// ============================================================
__global__ void k_scan() {
    int idx = blockIdx.x * blockDim.x + threadIdx.x;   // 0..32767
    int b  = idx >> 13;
    int r  = idx & 8191;
    int a  = r >> 7;             // residue class
    int d4 = r & 127;            // float4 index within DIM

    float4 acc = make_float4(0.f, 0.f, 0.f, 0.f);
    const float4* cbase = (const float4*)g_c;
    float4*       sbase = (float4*)g_S0;
    #pragma unroll 4
    for (int g = 0; g < NT; ++g) {
        size_t sidx = ((size_t)((b * NT + g) * ABS + a)) * (DIM / 4) + d4;
        sbase[sidx] = acc;                                   // exclusive
        size_t cidx = ((size_t)(b * NSEQ + g * ABS + a)) * (DIM / 4) + d4;
        float4 v = cbase[cidx];
        acc.x += v.x; acc.y += v.y; acc.z += v.z; acc.w += v.w;
    }
}

// ============================================================
// Kernel C: pooled[b, t*64+i, a] =
//   (1/64) * ( c_i . S0[t,a]  +  (a<=i) * c_i . c_a_local )
// One CTA per (b, t). 128 threads; each thread: 8m x 4n per GEMM
// (two GEMMs share the A fragment).
// ============================================================
#define KC 64
__global__ void __launch_bounds__(128) k_pooled() {
    __shared__ float cs[KC][68];   // K-major c tile
    __shared__ float ss[KC][68];   // K-major S0 tile

    int bt = blockIdx.x;
    int b = bt >> 6, t = bt & 63;
    const float* cbase = g_c  + ((size_t)b * NSEQ + t * ABS) * DIM;   // 64 x 512
    const float* sbase = g_S0 + ((size_t)(b * NT + t)) * ABS * DIM;   // 64 x 512

    int tid = threadIdx.x;
    int tx = tid & 15, ty = tid >> 4;   // tx: n-group of 4, ty: m-group of 8

    float ah[8][4], ad[8][4];
    #pragma unroll
    for (int m = 0; m < 8; ++m)
        #pragma unroll
        for (int n = 0; n < 4; ++n) { ah[m][n] = 0.f; ad[m][n] = 0.f; }

    for (int k0 = 0; k0 < DIM; k0 += KC) {
        // fill cs: 64 rows x 16 float4 = 1024 float4 / 128 threads = 8 each
        #pragma unroll
        for (int j = 0; j < 8; ++j) {
            int f = tid + 128 * j;           // 0..1023
            int row = f >> 4;                // 0..63
            int cq  = f & 15;
            float4 v = *(const float4*)(cbase + (size_t)row * DIM + k0 + cq * 4);
            cs[cq * 4 + 0][row] = v.x; cs[cq * 4 + 1][row] = v.y;
            cs[cq * 4 + 2][row] = v.z; cs[cq * 4 + 3][row] = v.w;
        }
        #pragma unroll
        for (int j = 0; j < 8; ++j) {
            int f = tid + 128 * j;
            int row = f >> 4;
            int cq  = f & 15;
            float4 w = *(const float4*)(sbase + (size_t)row * DIM + k0 + cq * 4);
            ss[cq * 4 + 0][row] = w.x; ss[cq * 4 + 1][row] = w.y;
            ss[cq * 4 + 2][row] = w.z; ss[cq * 4 + 3][row] = w.w;
        }
        __syncthreads();

        #pragma unroll 8
        for (int kk = 0; kk < KC; ++kk) {
            float4 a0 = *(const float4*)&cs[kk][ty * 8];
            float4 a1 = *(const float4*)&cs[kk][ty * 8 + 4];
            float4 bh = *(const float4*)&ss[kk][tx * 4];
            float4 bd = *(const float4*)&cs[kk][tx * 4];
            float a_[8] = {a0.x, a0.y, a0.z, a0.w, a1.x, a1.y, a1.z, a1.w};
            float h_[4] = {bh.x, bh.y, bh.z, bh.w};
            float d_[4] = {bd.x, bd.y, bd.z, bd.w};
            #pragma unroll
            for (int m = 0; m < 8; ++m)
                #pragma unroll
                for (int n = 0; n < 4; ++n) {
                    ah[m][n] = fmaf(a_[m], h_[n], ah[m][n]);
                    ad[m][n] = fmaf(a_[m], d_[n], ad[m][n]);
                }
        }
        __syncthreads();
    }

    // write pooled with causal diag mask and 1/64 scale
    const float scale = 1.0f / 64.0f;
    #pragma unroll
    for (int m = 0; m < 8; ++m) {
        int i = ty * 8 + m;
        float* orow = g_pooled + ((size_t)b * NSEQ + t * ABS + i) * ABS;
        float4 o;
        int j0 = tx * 4;
        o.x = (ah[m][0] + ((j0 + 0 <= i) ? ad[m][0] : 0.f)) * scale;
        o.y = (ah[m][1] + ((j0 + 1 <= i) ? ad[m][1] : 0.f)) * scale;
        o.z = (ah[m][2] + ((j0 + 2 <= i) ? ad[m][2] : 0.f)) * scale;
        o.w = (ah[m][3] + ((j0 + 3 <= i) ? ad[m][3] : 0.f)) * scale;
        *(float4*)&orow[j0] = o;
    }
}

// ============================================================
// Kernel Wc: W_comb[a, dout] = sum_k W_abs[a,k] * W_merge[512+k, dout]
// ============================================================
__global__ void k_wc(const float* __restrict__ Wabs, const float* __restrict__ Wm) {
    int idx = blockIdx.x * blockDim.x + threadIdx.x;   // 0..32767
    int a = idx >> 9;
    int dout = idx & 511;
    float acc = 0.f;
    #pragma unroll 8
    for (int k = 0; k < DIM; ++k)
        acc = fmaf(Wabs[a * DIM + k], Wm[(size_t)(DIM + k) * DIM + dout], acc);
    g_Wc[idx] = acc;
}

// ============================================================
// Kernel D: merged = data @ W1 + pooled @ W_comb, via bf16 tensor cores
// with error-compensated hi/lo split:
//   x = hi + lo;  A@B = hiA@hiB + hiA@loB + loA@hiB  (+ O(2^-18) dropped)
// Encoded as one bf16 GEMM over K' = 3K with slot pattern per original k:
//   slot 3k+0: (hiA, hiB)   slot 3k+1: (hiA, loB)   slot 3k+2: (loA, hiB)
// CTA 128x128, 256 threads (8 warps, 2x4), warp tile 64x32,
// mma.sync.aligned.m16n8k16 bf16 -> fp32.
// ============================================================
#define ASTR 72   // smem row stride in bf16 elems (144B -> conflict-free frags)

__device__ __forceinline__ void mma_bf16(float* d, const uint32_t* a, const uint32_t* b) {
    asm volatile(
        "mma.sync.aligned.m16n8k16.row.col.f32.bf16.bf16.f32 "
        "{%0,%1,%2,%3}, {%4,%5,%6,%7}, {%8,%9}, {%0,%1,%2,%3};\n"
        : "+f"(d[0]), "+f"(d[1]), "+f"(d[2]), "+f"(d[3])
        : "r"(a[0]), "r"(a[1]), "r"(a[2]), "r"(a[3]), "r"(b[0]), "r"(b[1]));
}

__global__ void __launch_bounds__(256) k_gemm_mma(const float* __restrict__ data,
                                                 const float* __restrict__ Wm,
                                                 float* __restrict__ out) {
    __shared__ __nv_bfloat16 As[128 * ASTR];   // [m][k'] , K' = 48 used
    __shared__ __nv_bfloat16 Bs[128 * ASTR];   // [n][k'] (k-contiguous for B frags)

    int tid = threadIdx.x;
    int wid = tid >> 5, lane = tid & 31;
    int gr = lane >> 2, tq = lane & 3;         // groupID, thread-in-group
    int warp_m = wid & 1, warp_n = wid >> 1;   // 2 x 4 warp grid
    int m0 = blockIdx.y * 128, n0 = blockIdx.x * 128;

    float acc[4][4][4];                        // [mt][nt][c0..c3]
    #pragma unroll
    for (int mt = 0; mt < 4; ++mt)
        #pragma unroll
        for (int nt = 0; nt < 4; ++nt)
            #pragma unroll
            for (int c = 0; c < 4; ++c) acc[mt][nt][c] = 0.f;

    #pragma unroll 1
    for (int phase = 0; phase < 2; ++phase) {
        const float* Ap = phase ? (g_pooled + (size_t)m0 * ABS) : (data + (size_t)m0 * DIM);
        const float* Bp = phase ? g_Wc : Wm;   // W1 = first 512 rows of W_merge
        int lda = phase ? ABS : DIM;
        int nchunks = phase ? (ABS / 16) : (DIM / 16);

        for (int ch = 0; ch < nchunks; ++ch) {
            int kc0 = ch * 16;
            // ---- fill A: 128 x 16 fp32 -> hi,hi,lo at slots 3k+{0,1,2} ----
            #pragma unroll
            for (int j = 0; j < 8; ++j) {
                int f = tid + 256 * j;         // 0..2047
                int m = f >> 4, k = f & 15;
                float v = Ap[(size_t)m * lda + kc0 + k];
                __nv_bfloat16 h = __float2bfloat16(v);
                __nv_bfloat16 l = __float2bfloat16(v - __bfloat162float(h));
                __nv_bfloat16* p = &As[m * ASTR + 3 * k];
                p[0] = h; p[1] = h; p[2] = l;
            }
            // ---- fill B: 16 x 128 fp32 -> hi,lo,hi (transposed to [n][k']) ----
            #pragma unroll
            for (int j = 0; j < 8; ++j) {
                int f = tid + 256 * j;
                int k = f >> 7, n = f & 127;
                float v = Bp[(size_t)(kc0 + k) * DIM + n0 + n];
                __nv_bfloat16 h = __float2bfloat16(v);
                __nv_bfloat16 l = __float2bfloat16(v - __bfloat162float(h));
                __nv_bfloat16* p = &Bs[n * ASTR + 3 * k];
                p[0] = h; p[1] = l; p[2] = h;
            }
            __syncthreads();

            // ---- 3 k16-steps over K' = 48 ----
            #pragma unroll
            for (int ks = 0; ks < 3; ++ks) {
                int kp = ks * 16;
                uint32_t bf[4][2];
                #pragma unroll
                for (int nt = 0; nt < 4; ++nt) {
                    const __nv_bfloat16* bp = &Bs[(warp_n * 32 + nt * 8 + gr) * ASTR + kp + 2 * tq];
                    bf[nt][0] = *(const uint32_t*)bp;
                    bf[nt][1] = *(const uint32_t*)(bp + 8);
                }
                #pragma unroll
                for (int mt = 0; mt < 4; ++mt) {
                    uint32_t af[4];
                    const __nv_bfloat16* ap = &As[(warp_m * 64 + mt * 16 + gr) * ASTR + kp + 2 * tq];
                    af[0] = *(const uint32_t*)ap;
                    af[1] = *(const uint32_t*)(ap + 8 * ASTR);
                    af[2] = *(const uint32_t*)(ap + 8);
                    af[3] = *(const uint32_t*)(ap + 8 * ASTR + 8);
                    #pragma unroll
                    for (int nt = 0; nt < 4; ++nt)
                        mma_bf16(acc[mt][nt], af, bf[nt]);
                }
            }
            __syncthreads();
        }
    }

    // ---- epilogue ----
    #pragma unroll
    for (int mt = 0; mt < 4; ++mt) {
        int r = m0 + warp_m * 64 + mt * 16 + gr;
        #pragma unroll
        for (int nt = 0; nt < 4; ++nt) {
            int c = n0 + warp_n * 32 + nt * 8 + 2 * tq;
            *(float2*)&out[(size_t)r * DIM + c]       = make_float2(acc[mt][nt][0], acc[mt][nt][1]);
            *(float2*)&out[(size_t)(r + 8) * DIM + c] = make_float2(acc[mt][nt][2], acc[mt][nt][3]);
        }
    }
}

// ============================================================
extern "C" void kernel_launch(void* const* d_in, const int* in_sizes, int n_in,
                              void* d_out, int out_size) {
    const float* data = (const float*)d_in[0];   // [4,4096,512]
    const float* Wabs = (const float*)d_in[1];   // [64,512]
    const float* Wm   = (const float*)d_in[2];   // [1024,512]
    float* out = (float*)d_out;                  // [4,4096,512]

    k_norm<<<BATCH * NSEQ, 128>>>(data);
    k_wc<<<128, 256>>>(Wabs, Wm);                // independent, tiny
    k_scan<<<128, 256>>>();
    k_pooled<<<BATCH * NT, 128>>>();
    k_gemm_mma<<<dim3(DIM / 128, BATCH * NSEQ / 128), 256>>>(data, Wm, out);
}

// round 5
// speedup vs baseline: 1.5275x; 1.3534x over previous
#include <cuda_runtime.h>
#include <cuda_bf16.h>
#include <cstdint>

#define BATCH 4
#define NSEQ  4096
#define DIM   512
#define ABS   64
#define NT    64          // tiles of 64 rows per batch (NSEQ/ABS)

// planar split-bf16 smem row geometry: K'=48 elems used, stride 56 elems (28 u32)
#define RSTRE 56
#define RSTRW 28

// -------- scratch (device globals; no runtime allocation) --------
__device__ float g_c[BATCH * NSEQ * DIM];        // normalized data (32 MB)
__device__ float g_S0[BATCH * NT * ABS * DIM];   // exclusive tile-prefix sums (32 MB)
__device__ float g_pooled[BATCH * NSEQ * ABS];   // [B,N,64] (4 MB)
__device__ float g_Wc[ABS * DIM];                // W_abs @ W_merge[512:1024] (128 KB)
// pre-converted B operand for k_gemm_mma: [4 nblk][36 chunks][128 n][56 k'] bf16 (~2 MB)
__device__ __nv_bfloat16 g_Bp[4 * 36 * 128 * RSTRE];

// -------- helpers --------
__device__ __forceinline__ uint32_t pack2(__nv_bfloat16 a, __nv_bfloat16 b) {
    return (uint32_t)__bfloat16_as_ushort(a) | ((uint32_t)__bfloat16_as_ushort(b) << 16);
}
__device__ __forceinline__ void split2(float2 v, uint32_t& hh, uint32_t& ll) {
    __nv_bfloat16 h0 = __float2bfloat16(v.x);
    __nv_bfloat16 h1 = __float2bfloat16(v.y);
    __nv_bfloat16 l0 = __float2bfloat16(v.x - __bfloat162float(h0));
    __nv_bfloat16 l1 = __float2bfloat16(v.y - __bfloat162float(h1));
    hh = pack2(h0, h1); ll = pack2(l0, l1);
}
__device__ __forceinline__ void mma_bf16(float* d, const uint32_t* a, const uint32_t* b) {
    asm volatile(
        "mma.sync.aligned.m16n8k16.row.col.f32.bf16.bf16.f32 "
        "{%0,%1,%2,%3}, {%4,%5,%6,%7}, {%8,%9}, {%0,%1,%2,%3};\n"
        : "+f"(d[0]), "+f"(d[1]), "+f"(d[2]), "+f"(d[3])
        : "r"(a[0]), "r"(a[1]), "r"(a[2]), "r"(a[3]), "r"(b[0]), "r"(b[1]));
}

// ============================================================
// Kernel A: L2 normalize rows of data -> g_c
// ============================================================
__global__ void k_norm(const float* __restrict__ data) {
    int row = blockIdx.x;                       // 0 .. 16383
    const float4* src = (const float4*)(data + (size_t)row * DIM);
    float4*       dst = (float4*)(g_c + (size_t)row * DIM);
    int t = threadIdx.x;

    float4 v = src[t];
    float s = v.x * v.x + v.y * v.y + v.z * v.z + v.w * v.w;
    #pragma unroll
    for (int off = 16; off > 0; off >>= 1)
        s += __shfl_xor_sync(0xFFFFFFFFu, s, off);

    __shared__ float ws[4];
    __shared__ float s_inv;
    int lane = t & 31, warp = t >> 5;
    if (lane == 0) ws[warp] = s;
    __syncthreads();
    if (t == 0) {
        float tot = ws[0] + ws[1] + ws[2] + ws[3];
        s_inv = rsqrtf(fmaxf(tot, 1e-12f));
    }
    __syncthreads();
    float iv = s_inv;
    v.x *= iv; v.y *= iv; v.z *= iv; v.w *= iv;
    dst[t] = v;
}

// ============================================================
// Kernel B: exclusive tile-prefix scan, scalar (one thread per (b,a,d))
// S0[b,t,a,:] = sum_{g<t} c[b, g*64+a, :]
// 131072 threads -> ~28 warps/SM to hide the dependent-load chain
// ============================================================
__global__ void k_scan() {
    int idx = blockIdx.x * blockDim.x + threadIdx.x;   // 0..131071
    int b = idx >> 15;
    int r = idx & 32767;
    int a = r >> 9;              // residue class
    int d = r & 511;             // scalar dim index

    float acc = 0.f;
    #pragma unroll 4
    for (int g = 0; g < NT; ++g) {
        g_S0[((size_t)((b * NT + g) * ABS + a)) * DIM + d] = acc;          // exclusive
        acc += g_c[((size_t)(b * NSEQ + g * ABS + a)) * DIM + d];
    }
}

// ============================================================
// Kernel Wc: W_comb[a, dout] = sum_k W_abs[a,k] * W_merge[512+k, dout]
// ============================================================
__global__ void k_wc(const float* __restrict__ Wabs, const float* __restrict__ Wm) {
    int idx = blockIdx.x * blockDim.x + threadIdx.x;   // 0..32767
    int a = idx >> 9;
    int dout = idx & 511;
    float acc = 0.f;
    #pragma unroll 8
    for (int k = 0; k < DIM; ++k)
        acc = fmaf(Wabs[a * DIM + k], Wm[(size_t)(DIM + k) * DIM + dout], acc);
    g_Wc[idx] = acc;
}

// ============================================================
// Kernel prepB: pre-convert the GEMM B operand (W1 rows 0..511 of W_merge,
// then W_comb) into planar split-bf16 layout [nb][ch][n][56]:
//   plane0 = hi, plane1 = lo, plane2 = hi   (pairs with A's hi,hi,lo)
// ============================================================
__global__ void k_prepB(const float* __restrict__ Wm) {
    int idx = blockIdx.x * blockDim.x + threadIdx.x;   // 0..294911
    int k   = idx & 15;
    int n   = (idx >> 4) & 127;
    int rest = idx >> 11;            // 0..143
    int ch  = rest % 36;
    int nb  = rest / 36;

    float v;
    if (ch < 32) v = Wm[(size_t)(ch * 16 + k) * DIM + nb * 128 + n];
    else         v = g_Wc[(size_t)((ch - 32) * 16 + k) * DIM + nb * 128 + n];

    __nv_bfloat16 h = __float2bfloat16(v);
    __nv_bfloat16 l = __float2bfloat16(v - __bfloat162float(h));
    __nv_bfloat16* p = &g_Bp[((size_t)(nb * 36 + ch) * 128 + n) * RSTRE + k];
    p[0]  = h;   // plane 0
    p[16] = l;   // plane 1
    p[32] = h;   // plane 2
}

// ============================================================
// Kernel C: pooled via tensor cores.
// One CTA per (b,t): P[64x128] = c_tile[64x512] @ [S0_tile ; c_tile]^T
// with split-bf16 (A planes hi,hi,lo ; B planes hi,lo,hi).
// 256 threads = 8 warps (2m x 4n), warp tile 32m x 16n per B-matrix.
// Epilogue: pooled[i][a] = (P_s0 + (a<=i)*P_local)/64.
// ============================================================
__global__ void __launch_bounds__(256) k_pooled() {
    __shared__ uint32_t AsW[64 * RSTRW];    // c as A   (7 KB)
    __shared__ uint32_t BsW[128 * RSTRW];   // [S0 ; c] as B (14 KB)
    __nv_bfloat16* As = (__nv_bfloat16*)AsW;
    __nv_bfloat16* Bs = (__nv_bfloat16*)BsW;

    int bt = blockIdx.x;
    int b = bt >> 6, t = bt & 63;
    const float* cbase = g_c  + ((size_t)b * NSEQ + t * ABS) * DIM;   // 64 x 512
    const float* sbase = g_S0 + ((size_t)(b * NT + t)) * ABS * DIM;   // 64 x 512

    int tid = threadIdx.x;
    int wid = tid >> 5, lane = tid & 31;
    int gr = lane >> 2, tq = lane & 3;
    int warp_m = wid & 1, warp_n = wid >> 1;   // 2 x 4

    float acc_h[2][2][4], acc_d[2][2][4];
    #pragma unroll
    for (int mt = 0; mt < 2; ++mt)
        #pragma unroll
        for (int nt = 0; nt < 2; ++nt)
            #pragma unroll
            for (int c = 0; c < 4; ++c) { acc_h[mt][nt][c] = 0.f; acc_d[mt][nt][c] = 0.f; }

    for (int ch = 0; ch < 32; ++ch) {
        int kc0 = ch * 16;
        // S0 fill -> Bs rows 0..63 (planes hi,lo,hi)
        #pragma unroll
        for (int jj = 0; jj < 2; ++jj) {
            int f = tid + 256 * jj;        // 0..511
            int k2 = f & 7, m = f >> 3;
            float2 v = *(const float2*)(sbase + (size_t)m * DIM + kc0 + 2 * k2);
            uint32_t hh, ll; split2(v, hh, ll);
            uint32_t* p = &BsW[m * RSTRW + k2];
            p[0] = hh; p[8] = ll; p[16] = hh;
        }
        // c fill -> As rows (planes hi,hi,lo) AND Bs rows 64..127 (hi,lo,hi)
        #pragma unroll
        for (int jj = 0; jj < 2; ++jj) {
            int f = tid + 256 * jj;
            int k2 = f & 7, m = f >> 3;
            float2 v = *(const float2*)(cbase + (size_t)m * DIM + kc0 + 2 * k2);
            uint32_t hh, ll; split2(v, hh, ll);
            uint32_t* pa = &AsW[m * RSTRW + k2];
            pa[0] = hh; pa[8] = hh; pa[16] = ll;
            uint32_t* pb = &BsW[(64 + m) * RSTRW + k2];
            pb[0] = hh; pb[8] = ll; pb[16] = hh;
        }
        __syncthreads();

        #pragma unroll
        for (int ks = 0; ks < 3; ++ks) {
            int kp = ks * 16;
            uint32_t bh[2][2], bd[2][2];
            #pragma unroll
            for (int nt = 0; nt < 2; ++nt) {
                int jrow = warp_n * 16 + nt * 8 + gr;
                const __nv_bfloat16* bp = &Bs[jrow * RSTRE + kp + 2 * tq];
                bh[nt][0] = *(const uint32_t*)bp;
                bh[nt][1] = *(const uint32_t*)(bp + 8);
                const __nv_bfloat16* dp = bp + 64 * RSTRE;
                bd[nt][0] = *(const uint32_t*)dp;
                bd[nt][1] = *(const uint32_t*)(dp + 8);
            }
            #pragma unroll
            for (int mt = 0; mt < 2; ++mt) {
                uint32_t af[4];
                const __nv_bfloat16* ap = &As[(warp_m * 32 + mt * 16 + gr) * RSTRE + kp + 2 * tq];
                af[0] = *(const uint32_t*)ap;
                af[1] = *(const uint32_t*)(ap + 8 * RSTRE);
                af[2] = *(const uint32_t*)(ap + 8);
                af[3] = *(const uint32_t*)(ap + 8 * RSTRE + 8);
                #pragma unroll
                for (int nt = 0; nt < 2; ++nt) {
                    mma_bf16(acc_h[mt][nt], af, bh[nt]);
                    mma_bf16(acc_d[mt][nt], af, bd[nt]);
                }
            }
        }
        __syncthreads();
    }

    // epilogue: combine + causal mask + 1/64
    const float scale = 1.0f / 64.0f;
    float* obase = g_pooled + ((size_t)b * NSEQ + t * ABS) * ABS;
    #pragma unroll
    for (int mt = 0; mt < 2; ++mt) {
        #pragma unroll
        for (int half = 0; half < 2; ++half) {       // c0,c1 vs c2,c3 (row, row+8)
            int i = warp_m * 32 + mt * 16 + gr + half * 8;
            #pragma unroll
            for (int nt = 0; nt < 2; ++nt) {
                int j = warp_n * 16 + nt * 8 + 2 * tq;
                float v0 = acc_h[mt][nt][half * 2 + 0] + ((j     <= i) ? acc_d[mt][nt][half * 2 + 0] : 0.f);
                float v1 = acc_h[mt][nt][half * 2 + 1] + ((j + 1 <= i) ? acc_d[mt][nt][half * 2 + 1] : 0.f);
                *(float2*)&obase[(size_t)i * ABS + j] = make_float2(v0 * scale, v1 * scale);
            }
        }
    }
}

// ============================================================
// Kernel D: merged = data @ W1 + pooled @ W_comb via bf16 split MMA.
// A converted in-kernel (planar, vectorized); B copied from g_Bp.
// CTA 128x128, 256 threads (2x4 warps), warp tile 64x32.
// ============================================================
__global__ void __launch_bounds__(256) k_gemm_mma(const float* __restrict__ data,
                                                 float* __restrict__ out) {
    __shared__ uint32_t AsW[128 * RSTRW];   // 14 KB
    __shared__ uint32_t BsW[128 * RSTRW];   // 14 KB
    __nv_bfloat16* As = (__nv_bfloat16*)AsW;
    __nv_bfloat16* Bs = (__nv_bfloat16*)BsW;

    int tid = threadIdx.x;
    int wid = tid >> 5, lane = tid & 31;
    int gr = lane >> 2, tq = lane & 3;
    int warp_m = wid & 1, warp_n = wid >> 1;   // 2 x 4
    int m0 = blockIdx.y * 128, nb = blockIdx.x;
    int n0 = nb * 128;

    float acc[4][4][4];
    #pragma unroll
    for (int mt = 0; mt < 4; ++mt)
        #pragma unroll
        for (int nt = 0; nt < 4; ++nt)
            #pragma unroll
            for (int c = 0; c < 4; ++c) acc[mt][nt][c] = 0.f;

    #pragma unroll 1
    for (int phase = 0; phase < 2; ++phase) {
        const float* Ap = phase ? (g_pooled + (size_t)m0 * ABS) : (data + (size_t)m0 * DIM);
        int lda = phase ? ABS : DIM;
        int nchunks = phase ? 4 : 32;
        int chbase = phase ? 32 : 0;

        for (int ch = 0; ch < nchunks; ++ch) {
            int kc0 = ch * 16;
            // ---- A: 128 x 16 fp32 -> planar hi,hi,lo (vectorized) ----
            #pragma unroll
            for (int jj = 0; jj < 4; ++jj) {
                int f = tid + 256 * jj;        // 0..1023
                int k2 = f & 7, m = f >> 3;
                float2 v = *(const float2*)(Ap + (size_t)m * lda + kc0 + 2 * k2);
                uint32_t hh, ll; split2(v, hh, ll);
                uint32_t* p = &AsW[m * RSTRW + k2];
                p[0] = hh; p[8] = hh; p[16] = ll;
            }
            // ---- B: straight 16B copy from pre-converted g_Bp ----
            {
                const uint4* src = (const uint4*)&g_Bp[(size_t)(nb * 36 + chbase + ch) * 128 * RSTRE];
                uint4* dst = (uint4*)BsW;
                #pragma unroll
                for (int jj = 0; jj < 4; ++jj) {
                    int f = tid + 256 * jj;    // 0..1023 ; need 896
                    if (f < 128 * RSTRW / 4) dst[f] = src[f];
                }
            }
            __syncthreads();

            #pragma unroll
            for (int ks = 0; ks < 3; ++ks) {
                int kp = ks * 16;
                uint32_t bf[4][2];
                #pragma unroll
                for (int nt = 0; nt < 4; ++nt) {
                    const __nv_bfloat16* bp = &Bs[(warp_n * 32 + nt * 8 + gr) * RSTRE + kp + 2 * tq];
                    bf[nt][0] = *(const uint32_t*)bp;
                    bf[nt][1] = *(const uint32_t*)(bp + 8);
                }
                #pragma unroll
                for (int mt = 0; mt < 4; ++mt) {
                    uint32_t af[4];
                    const __nv_bfloat16* ap = &As[(warp_m * 64 + mt * 16 + gr) * RSTRE + kp + 2 * tq];
                    af[0] = *(const uint32_t*)ap;
                    af[1] = *(const uint32_t*)(ap + 8 * RSTRE);
                    af[2] = *(const uint32_t*)(ap + 8);
                    af[3] = *(const uint32_t*)(ap + 8 * RSTRE + 8);
                    #pragma unroll
                    for (int nt = 0; nt < 4; ++nt)
                        mma_bf16(acc[mt][nt], af, bf[nt]);
                }
            }
            __syncthreads();
        }
    }

    // ---- epilogue ----
    #pragma unroll
    for (int mt = 0; mt < 4; ++mt) {
        int r = m0 + warp_m * 64 + mt * 16 + gr;
        #pragma unroll
        for (int nt = 0; nt < 4; ++nt) {
            int c = n0 + warp_n * 32 + nt * 8 + 2 * tq;
            *(float2*)&out[(size_t)r * DIM + c]       = make_float2(acc[mt][nt][0], acc[mt][nt][1]);
            *(float2*)&out[(size_t)(r + 8) * DIM + c] = make_float2(acc[mt][nt][2], acc[mt][nt][3]);
        }
    }
}

// ============================================================
extern "C" void kernel_launch(void* const* d_in, const int* in_sizes, int n_in,
                              void* d_out, int out_size) {
    const float* data = (const float*)d_in[0];   // [4,4096,512]
    const float* Wabs = (const float*)d_in[1];   // [64,512]
    const float* Wm   = (const float*)d_in[2];   // [1024,512]
    float* out = (float*)d_out;                  // [4,4096,512]

    k_norm<<<BATCH * NSEQ, 128>>>(data);
    k_wc<<<128, 256>>>(Wabs, Wm);
    k_prepB<<<1152, 256>>>(Wm);
    k_scan<<<512, 256>>>();
    k_pooled<<<BATCH * NT, 256>>>();
    k_gemm_mma<<<dim3(DIM / 128, BATCH * NSEQ / 128), 256>>>(data, out);
}

// round 7
// speedup vs baseline: 1.7416x; 1.1402x over previous
#include <cuda_runtime.h>
#include <cuda_bf16.h>
#include <cstdint>

#define BATCH 4
#define NSEQ  4096
#define DIM   512
#define ABS   64
#define NT    64          // tiles of 64 rows per batch (NSEQ/ABS)

// planar split-bf16 smem geometry: 2 planes (hi, lo) of 16 elems; row stride
// 40 bf16 = 20 u32 (covers all 32 banks across a warp's fragment load)
#define RSTRE 40
#define RSTRW 20

// -------- scratch (device globals; no runtime allocation) --------
__device__ float g_inv[BATCH * NSEQ];            // per-row inverse L2 norms (64 KB)
__device__ float g_S0[BATCH * NT * ABS * DIM];   // exclusive tile-prefix sums of c (32 MB)
__device__ float g_pooled[BATCH * NSEQ * ABS];   // [B,N,64] (4 MB)
__device__ float g_Wc[ABS * DIM];                // W_abs @ W_merge[512:1024] (128 KB)
// pre-converted B operand for k_gemm_mma: [4 nblk][36 chunks][128 n][40] bf16 (~1.5 MB)
__device__ __nv_bfloat16 g_Bp[4 * 36 * 128 * RSTRE];

// -------- helpers --------
__device__ __forceinline__ uint32_t pack2(__nv_bfloat16 a, __nv_bfloat16 b) {
    return (uint32_t)__bfloat16_as_ushort(a) | ((uint32_t)__bfloat16_as_ushort(b) << 16);
}
__device__ __forceinline__ void split2(float2 v, uint32_t& hh, uint32_t& ll) {
    __nv_bfloat16 h0 = __float2bfloat16(v.x);
    __nv_bfloat16 h1 = __float2bfloat16(v.y);
    __nv_bfloat16 l0 = __float2bfloat16(v.x - __bfloat162float(h0));
    __nv_bfloat16 l1 = __float2bfloat16(v.y - __bfloat162float(h1));
    hh = pack2(h0, h1); ll = pack2(l0, l1);
}
__device__ __forceinline__ void mma_bf16(float* d, const uint32_t* a, const uint32_t* b) {
    asm volatile(
        "mma.sync.aligned.m16n8k16.row.col.f32.bf16.bf16.f32 "
        "{%0,%1,%2,%3}, {%4,%5,%6,%7}, {%8,%9}, {%0,%1,%2,%3};\n"
        : "+f"(d[0]), "+f"(d[1]), "+f"(d[2]), "+f"(d[3])
        : "r"(a[0]), "r"(a[1]), "r"(a[2]), "r"(a[3]), "r"(b[0]), "r"(b[1]));
}

// ============================================================
// Kernel A: per-row inverse L2 norm only (one warp per row)
// ============================================================
__global__ void k_norms(const float* __restrict__ data) {
    int gw   = (blockIdx.x * blockDim.x + threadIdx.x) >> 5;   // 0..16383
    int lane = threadIdx.x & 31;
    const float4* src = (const float4*)(data + (size_t)gw * DIM);
    float s = 0.f;
    #pragma unroll
    for (int j = 0; j < 4; ++j) {
        float4 v = src[lane + 32 * j];
        s += v.x * v.x + v.y * v.y + v.z * v.z + v.w * v.w;
    }
    #pragma unroll
    for (int off = 16; off > 0; off >>= 1)
        s += __shfl_xor_sync(0xFFFFFFFFu, s, off);
    if (lane == 0) g_inv[gw] = rsqrtf(fmaxf(s, 1e-12f));
}

// ============================================================
// Kernel B: exclusive tile-prefix scan of normalized rows.
// 4 independent chains per thread: residues (a, a+32), float2 each.
// S0[b,t,a,:] = sum_{g<t} data[b, g*64+a, :] * inv_norm
// ============================================================
__global__ void k_scan(const float* __restrict__ data) {
    int idx = blockIdx.x * blockDim.x + threadIdx.x;   // 0..32767
    int b  = idx >> 13;
    int r  = idx & 8191;
    int a  = r >> 8;             // residue class 0..31 (chain 2 uses a+32)
    int d2 = r & 255;            // float2 index within DIM

    const float2* df2 = (const float2*)data;
    float2*       sf2 = (float2*)g_S0;

    float2 acc1 = make_float2(0.f, 0.f);
    float2 acc2 = make_float2(0.f, 0.f);
    #pragma unroll 4
    for (int g = 0; g < NT; ++g) {
        int row1 = b * NSEQ + g * ABS + a;
        int row2 = row1 + 32;
        size_t s1 = ((size_t)((b * NT + g) * ABS + a)) * 256 + d2;
        sf2[s1]                = acc1;                       // exclusive
        sf2[s1 + 32 * 256]     = acc2;
        float iv1 = g_inv[row1];
        float iv2 = g_inv[row2];
        float2 v1 = df2[(size_t)row1 * 256 + d2];
        float2 v2 = df2[(size_t)row2 * 256 + d2];
        acc1.x += v1.x * iv1; acc1.y += v1.y * iv1;
        acc2.x += v2.x * iv2; acc2.y += v2.y * iv2;
    }
}

// ============================================================
// Kernel Wc: W_comb[a, dout] = sum_k W_abs[a,k] * W_merge[512+k, dout]
// ============================================================
__global__ void k_wc(const float* __restrict__ Wabs, const float* __restrict__ Wm) {
    int idx = blockIdx.x * blockDim.x + threadIdx.x;   // 0..32767
    int a = idx >> 9;
    int dout = idx & 511;
    float acc = 0.f;
    #pragma unroll 8
    for (int k = 0; k < DIM; ++k)
        acc = fmaf(Wabs[a * DIM + k], Wm[(size_t)(DIM + k) * DIM + dout], acc);
    g_Wc[idx] = acc;
}

// ============================================================
// Kernel prepB: pre-convert GEMM B operand into 2-plane split-bf16
// [nb][ch][n][40]: elems 0..15 = hi, elems 16..31 = lo
// ============================================================
__global__ void k_prepB(const float* __restrict__ Wm) {
    int idx = blockIdx.x * blockDim.x + threadIdx.x;   // 0..294911
    int k   = idx & 15;
    int n   = (idx >> 4) & 127;
    int rest = idx >> 11;            // 0..143
    int ch  = rest % 36;
    int nb  = rest / 36;

    float v;
    if (ch < 32) v = Wm[(size_t)(ch * 16 + k) * DIM + nb * 128 + n];
    else         v = g_Wc[(size_t)((ch - 32) * 16 + k) * DIM + nb * 128 + n];

    __nv_bfloat16 h = __float2bfloat16(v);
    __nv_bfloat16 l = __float2bfloat16(v - __bfloat162float(h));
    __nv_bfloat16* p = &g_Bp[((size_t)(nb * 36 + ch) * 128 + n) * RSTRE + k];
    p[0]  = h;   // hi plane
    p[16] = l;   // lo plane
}

// ============================================================
// Kernel C: pooled via tensor cores, double-buffered smem.
// One CTA per (b,t): P[64x128] = c_tile[64x512] @ [S0_tile ; c_tile]^T
// (c scaled on the fly from raw data by inv_norm).
// Per k-step plane remap: ks0=(A.hi,B.hi), ks1=(A.hi,B.lo), ks2=(A.lo,B.hi)
// ============================================================
__device__ __forceinline__ void pooled_fill(
    uint32_t* AsW, uint32_t* BsW,
    const float* cbase, const float* sbase, const float* ivs,
    int kc0, int tid)
{
    #pragma unroll
    for (int jj = 0; jj < 2; ++jj) {
        int f = tid + 256 * jj;        // 0..511
        int k2 = f & 7, m = f >> 3;
        float2 v = *(const float2*)(sbase + (size_t)m * DIM + kc0 + 2 * k2);
        uint32_t hh, ll; split2(v, hh, ll);
        uint32_t* p = &BsW[m * RSTRW + k2];
        p[0] = hh; p[8] = ll;
    }
    #pragma unroll
    for (int jj = 0; jj < 2; ++jj) {
        int f = tid + 256 * jj;
        int k2 = f & 7, m = f >> 3;
        float2 v = *(const float2*)(cbase + (size_t)m * DIM + kc0 + 2 * k2);
        float iv = ivs[m];
        v.x *= iv; v.y *= iv;
        uint32_t hh, ll; split2(v, hh, ll);
        uint32_t* pa = &AsW[m * RSTRW + k2];
        pa[0] = hh; pa[8] = ll;
        uint32_t* pb = &BsW[(64 + m) * RSTRW + k2];
        pb[0] = hh; pb[8] = ll;
    }
}

__global__ void __launch_bounds__(256) k_pooled(const float* __restrict__ data) {
    __shared__ uint32_t AsW[2][64 * RSTRW];    // c as A   (2 x 5 KB)
    __shared__ uint32_t BsW[2][128 * RSTRW];   // [S0 ; c] as B (2 x 10 KB)
    __shared__ float    ivs[64];

    int bt = blockIdx.x;
    int b = bt >> 6, t = bt & 63;
    const float* cbase = data + ((size_t)b * NSEQ + t * ABS) * DIM;   // raw 64 x 512
    const float* sbase = g_S0 + ((size_t)(b * NT + t)) * ABS * DIM;   // 64 x 512

    int tid = threadIdx.x;
    int wid = tid >> 5, lane = tid & 31;
    int gr = lane >> 2, tq = lane & 3;
    int warp_m = wid & 1, warp_n = wid >> 1;   // 2 x 4

    if (tid < 64) ivs[tid] = g_inv[b * NSEQ + t * ABS + tid];
    __syncthreads();

    float acc_h[2][2][4], acc_d[2][2][4];
    #pragma unroll
    for (int mt = 0; mt < 2; ++mt)
        #pragma unroll
        for (int nt = 0; nt < 2; ++nt)
            #pragma unroll
            for (int c = 0; c < 4; ++c) { acc_h[mt][nt][c] = 0.f; acc_d[mt][nt][c] = 0.f; }

    pooled_fill(AsW[0], BsW[0], cbase, sbase, ivs, 0, tid);
    __syncthreads();

    for (int ch = 0; ch < 32; ++ch) {
        int cur = ch & 1;
        if (ch + 1 < 32)
            pooled_fill(AsW[cur ^ 1], BsW[cur ^ 1], cbase, sbase, ivs, (ch + 1) * 16, tid);

        const __nv_bfloat16* As = (const __nv_bfloat16*)AsW[cur];
        const __nv_bfloat16* Bs = (const __nv_bfloat16*)BsW[cur];
        #pragma unroll
        for (int ks = 0; ks < 3; ++ks) {
            int ka = (ks == 2) ? 16 : 0;   // A plane offset (bf16 elems)
            int kb = (ks == 1) ? 16 : 0;   // B plane offset
            uint32_t bh[2][2], bd[2][2];
            #pragma unroll
            for (int nt = 0; nt < 2; ++nt) {
                int jrow = warp_n * 16 + nt * 8 + gr;
                const __nv_bfloat16* bp = &Bs[jrow * RSTRE + kb + 2 * tq];
                bh[nt][0] = *(const uint32_t*)bp;
                bh[nt][1] = *(const uint32_t*)(bp + 8);
                const __nv_bfloat16* dp = bp + 64 * RSTRE;
                bd[nt][0] = *(const uint32_t*)dp;
                bd[nt][1] = *(const uint32_t*)(dp + 8);
            }
            #pragma unroll
            for (int mt = 0; mt < 2; ++mt) {
                uint32_t af[4];
                const __nv_bfloat16* ap = &As[(warp_m * 32 + mt * 16 + gr) * RSTRE + ka + 2 * tq];
                af[0] = *(const uint32_t*)ap;
                af[1] = *(const uint32_t*)(ap + 8 * RSTRE);
                af[2] = *(const uint32_t*)(ap + 8);
                af[3] = *(const uint32_t*)(ap + 8 * RSTRE + 8);
                #pragma unroll
                for (int nt = 0; nt < 2; ++nt) {
                    mma_bf16(acc_h[mt][nt], af, bh[nt]);
                    mma_bf16(acc_d[mt][nt], af, bd[nt]);
                }
            }
        }
        __syncthreads();
    }

    // epilogue: combine + causal mask + 1/64
    const float scale = 1.0f / 64.0f;
    float* obase = g_pooled + ((size_t)b * NSEQ + t * ABS) * ABS;
    #pragma unroll
    for (int mt = 0; mt < 2; ++mt) {
        #pragma unroll
        for (int half = 0; half < 2; ++half) {
            int i = warp_m * 32 + mt * 16 + gr + half * 8;
            #pragma unroll
            for (int nt = 0; nt < 2; ++nt) {
                int j = warp_n * 16 + nt * 8 + 2 * tq;
                float v0 = acc_h[mt][nt][half * 2 + 0] + ((j     <= i) ? acc_d[mt][nt][half * 2 + 0] : 0.f);
                float v1 = acc_h[mt][nt][half * 2 + 1] + ((j + 1 <= i) ? acc_d[mt][nt][half * 2 + 1] : 0.f);
                *(float2*)&obase[(size_t)i * ABS + j] = make_float2(v0 * scale, v1 * scale);
            }
        }
    }
}

// ============================================================
// Kernel D: merged = data @ W1 + pooled @ W_comb via bf16 split MMA.
// Double-buffered smem (2 x 20 KB = 40 KB, fits static limit);
// unified 36-chunk pipeline across both phases.
// ============================================================
__device__ __forceinline__ void gemm_fill(
    uint32_t* AsW, uint32_t* BsW,
    const float* __restrict__ data, int m0, int nb, int ch36, int tid)
{
    const float* Ap; int lda, kc0;
    if (ch36 < 32) { Ap = data + (size_t)m0 * DIM;     lda = DIM; kc0 = ch36 * 16; }
    else           { Ap = g_pooled + (size_t)m0 * ABS; lda = ABS; kc0 = (ch36 - 32) * 16; }

    #pragma unroll
    for (int jj = 0; jj < 4; ++jj) {
        int f = tid + 256 * jj;        // 0..1023
        int k2 = f & 7, m = f >> 3;
        float2 v = *(const float2*)(Ap + (size_t)m * lda + kc0 + 2 * k2);
        uint32_t hh, ll; split2(v, hh, ll);
        uint32_t* p = &AsW[m * RSTRW + k2];
        p[0] = hh; p[8] = ll;
    }
    const uint4* src = (const uint4*)&g_Bp[(size_t)(nb * 36 + ch36) * 128 * RSTRE];
    uint4* dst = (uint4*)BsW;
    #pragma unroll
    for (int jj = 0; jj < 3; ++jj) {
        int f = tid + 256 * jj;        // need 640 (= 128*20/4)
        if (f < 128 * RSTRW / 4) dst[f] = src[f];
    }
}

__global__ void __launch_bounds__(256) k_gemm_mma(const float* __restrict__ data,
                                                 float* __restrict__ out) {
    __shared__ uint32_t AsW[2][128 * RSTRW];   // 2 x 10 KB
    __shared__ uint32_t BsW[2][128 * RSTRW];   // 2 x 10 KB

    int tid = threadIdx.x;
    int wid = tid >> 5, lane = tid & 31;
    int gr = lane >> 2, tq = lane & 3;
    int warp_m = wid & 1, warp_n = wid >> 1;   // 2 x 4
    int m0 = blockIdx.y * 128, nb = blockIdx.x;
    int n0 = nb * 128;

    float acc[4][4][4];
    #pragma unroll
    for (int mt = 0; mt < 4; ++mt)
        #pragma unroll
        for (int nt = 0; nt < 4; ++nt)
            #pragma unroll
            for (int c = 0; c < 4; ++c) acc[mt][nt][c] = 0.f;

    gemm_fill(AsW[0], BsW[0], data, m0, nb, 0, tid);
    __syncthreads();

    for (int ch = 0; ch < 36; ++ch) {
        int cur = ch & 1;
        if (ch + 1 < 36)
            gemm_fill(AsW[cur ^ 1], BsW[cur ^ 1], data, m0, nb, ch + 1, tid);

        const __nv_bfloat16* As = (const __nv_bfloat16*)AsW[cur];
        const __nv_bfloat16* Bs = (const __nv_bfloat16*)BsW[cur];
        #pragma unroll
        for (int ks = 0; ks < 3; ++ks) {
            int ka = (ks == 2) ? 16 : 0;   // A plane offset (bf16 elems)
            int kb = (ks == 1) ? 16 : 0;   // B plane offset
            uint32_t bf[4][2];
            #pragma unroll
            for (int nt = 0; nt < 4; ++nt) {
                const __nv_bfloat16* bp = &Bs[(warp_n * 32 + nt * 8 + gr) * RSTRE + kb + 2 * tq];
                bf[nt][0] = *(const uint32_t*)bp;
                bf[nt][1] = *(const uint32_t*)(bp + 8);
            }
            #pragma unroll
            for (int mt = 0; mt < 4; ++mt) {
                uint32_t af[4];
                const __nv_bfloat16* ap = &As[(warp_m * 64 + mt * 16 + gr) * RSTRE + ka + 2 * tq];
                af[0] = *(const uint32_t*)ap;
                af[1] = *(const uint32_t*)(ap + 8 * RSTRE);
                af[2] = *(const uint32_t*)(ap + 8);
                af[3] = *(const uint32_t*)(ap + 8 * RSTRE + 8);
                #pragma unroll
                for (int nt = 0; nt < 4; ++nt)
                    mma_bf16(acc[mt][nt], af, bf[nt]);
            }
        }
        __syncthreads();
    }

    // ---- epilogue ----
    #pragma unroll
    for (int mt = 0; mt < 4; ++mt) {
        int r = m0 + warp_m * 64 + mt * 16 + gr;
        #pragma unroll
        for (int nt = 0; nt < 4; ++nt) {
            int c = n0 + warp_n * 32 + nt * 8 + 2 * tq;
            *(float2*)&out[(size_t)r * DIM + c]       = make_float2(acc[mt][nt][0], acc[mt][nt][1]);
            *(float2*)&out[(size_t)(r + 8) * DIM + c] = make_float2(acc[mt][nt][2], acc[mt][nt][3]);
        }
    }
}

// ============================================================
extern "C" void kernel_launch(void* const* d_in, const int* in_sizes, int n_in,
                              void* d_out, int out_size) {
    const float* data = (const float*)d_in[0];   // [4,4096,512]
    const float* Wabs = (const float*)d_in[1];   // [64,512]
    const float* Wm   = (const float*)d_in[2];   // [1024,512]
    float* out = (float*)d_out;                  // [4,4096,512]

    k_norms<<<2048, 256>>>(data);
    k_wc<<<128, 256>>>(Wabs, Wm);
    k_prepB<<<1152, 256>>>(Wm);
    k_scan<<<128, 256>>>(data);
    k_pooled<<<BATCH * NT, 256>>>(data);
    k_gemm_mma<<<dim3(DIM / 128, BATCH * NSEQ / 128), 256>>>(data, out);
}